// round 2
// baseline (speedup 1.0000x reference)
#include <cuda_runtime.h>

#define DDIM 4096
#define RC 8
#define NTHREADS 512
#define GRID 148

// Scratch (allocation-free): transposed normalized u [i][k], and S matrix (d = S c)
__device__ float g_un[RC * DDIM];
__device__ float g_S[RC * RC];

// ---------------------------------------------------------------------------
// Prep kernel: single block. Computes column norms + Gram matrix of hra_u,
// the compact-WY combining matrix S (d = S c, where c = U^T x and
// x_out = x - U d reproduces the 8 sequential reflections), and writes the
// transposed normalized u into g_un.
// ---------------------------------------------------------------------------
__global__ void hra_prep_kernel(const float* __restrict__ hra_u) {
    __shared__ float gsh[36];
    __shared__ float rn[8];
    int tid = threadIdx.x;  // 256 threads

    if (tid < 36) gsh[tid] = 0.f;
    __syncthreads();

    // Upper-triangular Gram accumulators (raw, unnormalized)
    float acc[36];
#pragma unroll
    for (int t = 0; t < 36; t++) acc[t] = 0.f;

    for (int k = tid; k < DDIM; k += 256) {
        float4 a = reinterpret_cast<const float4*>(hra_u)[k * 2];
        float4 b = reinterpret_cast<const float4*>(hra_u)[k * 2 + 1];
        float v[8] = {a.x, a.y, a.z, a.w, b.x, b.y, b.z, b.w};
        int t = 0;
#pragma unroll
        for (int i = 0; i < 8; i++)
#pragma unroll
            for (int j = i; j < 8; j++)
                acc[t++] += v[i] * v[j];
    }

#pragma unroll
    for (int t = 0; t < 36; t++) {
#pragma unroll
        for (int o = 16; o > 0; o >>= 1)
            acc[t] += __shfl_xor_sync(0xffffffffu, acc[t], o);
    }
    if ((tid & 31) == 0) {
        for (int t = 0; t < 36; t++) atomicAdd(&gsh[t], acc[t]);
    }
    __syncthreads();

    if (tid == 0) {
        float G[8][8];
        int t = 0;
        for (int i = 0; i < 8; i++)
            for (int j = i; j < 8; j++) {
                G[i][j] = gsh[t];
                G[j][i] = gsh[t];
                t++;
            }
        float rnl[8];
        for (int i = 0; i < 8; i++) rnl[i] = rsqrtf(G[i][i]);
        for (int i = 0; i < 8; i++) rn[i] = rnl[i];
        float Gn[8][8];
        for (int i = 0; i < 8; i++)
            for (int j = 0; j < 8; j++)
                Gn[i][j] = G[i][j] * rnl[i] * rnl[j];
        // Sequential reflections: x <- x - 2 (u_i . x) u_i for i = 0..7.
        // Composite: x_out = x - U d with d = S c, c = U^T x.
        // Forward-substitution: for each unit column c of the identity,
        // solve (I + 2 L) x = 2 e_c where L[i][j] = Gn[j][i] for j < i.
        for (int c = 0; c < 8; c++) {
            float x[8];
            for (int i = 0; i < 8; i++) {
                float s = (i == c) ? 2.f : 0.f;
                for (int j = 0; j < i; j++) s -= 2.f * Gn[j][i] * x[j];
                x[i] = s;
            }
            for (int i = 0; i < 8; i++) g_S[i * 8 + c] = x[i];
        }
    }
    __syncthreads();

    // Write transposed normalized u: g_un[i][k] = hra_u[k][i] / norm_i
    for (int i = 0; i < 8; i++) {
        float r = rn[i];
        for (int k = tid; k < DDIM; k += 256)
            g_un[i * DDIM + k] = hra_u[k * 8 + i] * r;
    }
}

// ---------------------------------------------------------------------------
// Main kernel: persistent, one CTA/SM, u staged once in smem.
// Processes 4 rows ("quad") per iteration: c = U^T x (block dot), d = S c,
// x_out = x - sum_i d_i u_i. Single read + single write of X.
// smem: su[8][4096] | wsum[16][32] | dsh[32] | Ssh[64]
// ---------------------------------------------------------------------------
extern __shared__ float smem[];

__global__ void __launch_bounds__(NTHREADS, 1)
hra_main_kernel(const float* __restrict__ X, float* __restrict__ Y, int nquads) {
    float* su = smem;                       // 8*4096 floats
    float* wsum = smem + 8 * DDIM;          // 16*32
    float* dsh = wsum + 16 * 32;            // 32
    float* Ssh = dsh + 32;                  // 64

    const int tid = threadIdx.x;
    const int lane = tid & 31;
    const int warp = tid >> 5;

    // Stage u (transposed) and S into shared
    {
        const float4* gu4 = reinterpret_cast<const float4*>(g_un);
        float4* su4 = reinterpret_cast<float4*>(su);
        for (int idx = tid; idx < 8 * (DDIM / 4); idx += NTHREADS)
            su4[idx] = gu4[idx];
        if (tid < 64) Ssh[tid] = g_S[tid];
    }
    __syncthreads();

    const float4* su4 = reinterpret_cast<const float4*>(su);

    for (int q = blockIdx.x; q < nquads; q += gridDim.x) {
        const size_t row0 = (size_t)q * 4;
        const float4* x4 = reinterpret_cast<const float4*>(X + row0 * DDIM);

        // Load 4 rows: thread owns float4 chunks [tid] and [tid+512] of each row
        float4 v[4][2];
#pragma unroll
        for (int r = 0; r < 4; r++) {
            v[r][0] = x4[r * 1024 + tid];
            v[r][1] = x4[r * 1024 + tid + NTHREADS];
        }

        // Partial dots: acc[r][i] = <x_r chunk, u_i chunk>
        float acc[4][8];
#pragma unroll
        for (int i = 0; i < 8; i++) {
            float4 s0 = su4[i * 1024 + tid];
            float4 s1 = su4[i * 1024 + tid + NTHREADS];
#pragma unroll
            for (int r = 0; r < 4; r++) {
                acc[r][i] = v[r][0].x * s0.x + v[r][0].y * s0.y +
                            v[r][0].z * s0.z + v[r][0].w * s0.w +
                            v[r][1].x * s1.x + v[r][1].y * s1.y +
                            v[r][1].z * s1.z + v[r][1].w * s1.w;
            }
        }

        // Warp reduce all 32 partial dots
#pragma unroll
        for (int r = 0; r < 4; r++)
#pragma unroll
            for (int i = 0; i < 8; i++)
#pragma unroll
                for (int o = 16; o > 0; o >>= 1)
                    acc[r][i] += __shfl_xor_sync(0xffffffffu, acc[r][i], o);

        if (lane == 0) {
#pragma unroll
            for (int r = 0; r < 4; r++)
#pragma unroll
                for (int i = 0; i < 8; i++)
                    wsum[warp * 32 + r * 8 + i] = acc[r][i];
        }
        __syncthreads();

        // Warp 0: finish reduction (c), apply S -> d, publish d
        if (warp == 0) {
            float c = 0.f;
#pragma unroll
            for (int w = 0; w < 16; w++) c += wsum[w * 32 + lane];
            const int i = lane & 7;
            float d = 0.f;
#pragma unroll
            for (int j = 0; j < 8; j++) {
                float cj = __shfl_sync(0xffffffffu, c, (lane & 24) + j);
                d += Ssh[i * 8 + j] * cj;
            }
            dsh[lane] = d;
        }
        __syncthreads();

        float dr[4][8];
#pragma unroll
        for (int r = 0; r < 4; r++)
#pragma unroll
            for (int i = 0; i < 8; i++)
                dr[r][i] = dsh[r * 8 + i];

        // Update: x -= sum_i d_i * u_i
#pragma unroll
        for (int i = 0; i < 8; i++) {
            float4 s0 = su4[i * 1024 + tid];
            float4 s1 = su4[i * 1024 + tid + NTHREADS];
#pragma unroll
            for (int r = 0; r < 4; r++) {
                float dd = dr[r][i];
                v[r][0].x -= dd * s0.x; v[r][0].y -= dd * s0.y;
                v[r][0].z -= dd * s0.z; v[r][0].w -= dd * s0.w;
                v[r][1].x -= dd * s1.x; v[r][1].y -= dd * s1.y;
                v[r][1].z -= dd * s1.z; v[r][1].w -= dd * s1.w;
            }
        }

        float4* y4 = reinterpret_cast<float4*>(Y + row0 * DDIM);
#pragma unroll
        for (int r = 0; r < 4; r++) {
            y4[r * 1024 + tid] = v[r][0];
            y4[r * 1024 + tid + NTHREADS] = v[r][1];
        }
    }
}

extern "C" void kernel_launch(void* const* d_in, const int* in_sizes, int n_in,
                              void* d_out, int out_size) {
    const float* X = (const float*)d_in[0];        // (4, 2048, 4096) fp32
    const float* hra_u = (const float*)d_in[1];    // (4096, 8) fp32
    float* Y = (float*)d_out;

    const int nrows = in_sizes[0] / DDIM;          // 8192
    const int nquads = nrows / 4;                  // 2048

    const size_t smem_bytes = (8 * DDIM + 16 * 32 + 32 + 64) * sizeof(float);  // 133504
    cudaFuncSetAttribute(hra_main_kernel,
                         cudaFuncAttributeMaxDynamicSharedMemorySize,
                         (int)smem_bytes);

    hra_prep_kernel<<<1, 256>>>(hra_u);
    hra_main_kernel<<<GRID, NTHREADS, smem_bytes>>>(X, Y, nquads);
}

// round 3
// speedup vs baseline: 1.0599x; 1.0599x over previous
#include <cuda_runtime.h>

#define DDIM 4096
#define NTHREADS 512
#define GRID 148

// ---------------------------------------------------------------------------
// Single persistent kernel.
// Phase 0 (per-CTA, redundant): read hra_u (128KB, L2-broadcast across CTAs),
//   compute Gram matrix, column norms, compact-WY matrix S = 2*(I+2L)^{-1}
//   (d = S c, c = U^T x, x_out = x - U d == 8 sequential reflections),
//   and stage transposed normalized u into smem.
// Phase 1: grid-strided quads of 4 rows. Per quad:
//   prefetch next quad's x (reg double-buffer) -> dots -> 5-stage multi-value
//   butterfly (31 shfl) -> per-lane STS -> bar -> warp0 finishes + applies S
//   -> bar -> rank-8 update -> streaming store.
// smem: su[8][4096] | wsum[16*32] | dsh[32] | Ssh[64] | gsh[36] | Gn[64] | rn[8]
// ---------------------------------------------------------------------------
extern __shared__ float smem[];

__device__ __forceinline__ int tri_idx(int a, int b) {
    // index into upper-triangular packed [36], requires a <= b
    return a * (17 - a) / 2 + (b - a);
}

__global__ void __launch_bounds__(NTHREADS, 1)
hra_kernel(const float* __restrict__ X, const float* __restrict__ hra_u,
           float* __restrict__ Y, int nquads) {
    float* su   = smem;                    // 8*4096
    float* wsum = su + 8 * DDIM;           // 16*32
    float* dsh  = wsum + 16 * 32;          // 32
    float* Ssh  = dsh + 32;                // 64
    float* gsh  = Ssh + 64;                // 36
    float* Gn   = gsh + 36;                // 64
    float* rn   = Gn + 64;                 // 8

    const int tid  = threadIdx.x;
    const int lane = tid & 31;
    const int warp = tid >> 5;

    // ---------------- Phase 0: Gram + S + stage u ----------------
    if (tid < 36) gsh[tid] = 0.f;
    __syncthreads();
    {
        float acc[36];
#pragma unroll
        for (int t = 0; t < 36; t++) acc[t] = 0.f;
        for (int k = tid; k < DDIM; k += NTHREADS) {
            float4 a = reinterpret_cast<const float4*>(hra_u)[k * 2];
            float4 b = reinterpret_cast<const float4*>(hra_u)[k * 2 + 1];
            float v[8] = {a.x, a.y, a.z, a.w, b.x, b.y, b.z, b.w};
            int t = 0;
#pragma unroll
            for (int i = 0; i < 8; i++)
#pragma unroll
                for (int j = i; j < 8; j++)
                    acc[t++] += v[i] * v[j];
        }
#pragma unroll
        for (int t = 0; t < 36; t++) {
#pragma unroll
            for (int o = 16; o > 0; o >>= 1)
                acc[t] += __shfl_xor_sync(0xffffffffu, acc[t], o);
        }
        if (lane == 0)
            for (int t = 0; t < 36; t++) atomicAdd(&gsh[t], acc[t]);
    }
    __syncthreads();
    if (tid < 8) rn[tid] = rsqrtf(gsh[tri_idx(tid, tid)]);
    __syncthreads();
    if (tid < 64) {
        int i = tid >> 3, j = tid & 7;
        int a = i < j ? i : j, b = i < j ? j : i;
        Gn[tid] = gsh[tri_idx(a, b)] * rn[i] * rn[j];
    }
    __syncthreads();
    if (tid < 8) {
        // forward substitution, column c = tid of S: (I + 2L) x = 2 e_c
        const int c = tid;
        float x[8];
#pragma unroll
        for (int i = 0; i < 8; i++) {
            float s = (i == c) ? 2.f : 0.f;
            for (int j = 0; j < i; j++) s -= 2.f * Gn[j * 8 + i] * x[j];
            x[i] = s;
            Ssh[i * 8 + c] = x[i];
        }
    }
    // Stage transposed normalized u (needs rn; Ssh written concurrently is fine)
    for (int k = tid; k < DDIM; k += NTHREADS) {
        float4 a = reinterpret_cast<const float4*>(hra_u)[k * 2];
        float4 b = reinterpret_cast<const float4*>(hra_u)[k * 2 + 1];
        float v[8] = {a.x, a.y, a.z, a.w, b.x, b.y, b.z, b.w};
#pragma unroll
        for (int i = 0; i < 8; i++)
            su[i * DDIM + k] = v[i] * rn[i];
    }
    __syncthreads();

    // ---------------- Phase 1: main loop ----------------
    const float4* su4 = reinterpret_cast<const float4*>(su);
    const int t_self = (int)(__brev((unsigned)lane) >> 27);  // bitrev5(lane)

    int q = blockIdx.x;
    if (q >= nquads) return;

    // preload first quad
    float4 v[4][2];
    {
        const float4* x4 = reinterpret_cast<const float4*>(X) + (size_t)q * 4096;
#pragma unroll
        for (int r = 0; r < 4; r++) {
            v[r][0] = __ldcs(&x4[r * 1024 + tid]);
            v[r][1] = __ldcs(&x4[r * 1024 + tid + NTHREADS]);
        }
    }

    for (; q < nquads; q += GRID) {
        // prefetch next quad (clamped address; discarded on last iter)
        int qn = q + GRID;
        int qc = qn < nquads ? qn : q;
        float4 v2[4][2];
        {
            const float4* x4n = reinterpret_cast<const float4*>(X) + (size_t)qc * 4096;
#pragma unroll
            for (int r = 0; r < 4; r++) {
                v2[r][0] = __ldcs(&x4n[r * 1024 + tid]);
                v2[r][1] = __ldcs(&x4n[r * 1024 + tid + NTHREADS]);
            }
        }

        // partial dots: val[r*8+i] = <x_r chunk, u_i chunk>
        float val[32];
#pragma unroll
        for (int i = 0; i < 8; i++) {
            float4 s0 = su4[i * 1024 + tid];
            float4 s1 = su4[i * 1024 + tid + NTHREADS];
#pragma unroll
            for (int r = 0; r < 4; r++) {
                val[r * 8 + i] =
                    v[r][0].x * s0.x + v[r][0].y * s0.y +
                    v[r][0].z * s0.z + v[r][0].w * s0.w +
                    v[r][1].x * s1.x + v[r][1].y * s1.y +
                    v[r][1].z * s1.z + v[r][1].w * s1.w;
            }
        }

        // multi-value butterfly: 31 shfl total; lane ends with sum of
        // val[bitrev5(lane)] over all 32 lanes
#pragma unroll
        for (int s = 0; s < 5; s++) {
            const int m = 1 << s;
            const int h = 16 >> s;
#pragma unroll
            for (int k = 0; k < h; k++) {
                float send = (lane & m) ? val[k] : val[k + h];
                float rec  = __shfl_xor_sync(0xffffffffu, send, m);
                float keep = (lane & m) ? val[k + h] : val[k];
                val[k] = keep + rec;
            }
        }
        wsum[warp * 32 + t_self] = val[0];
        __syncthreads();

        // warp 0: finish cross-warp reduction (c), apply S -> d, publish
        if (warp == 0) {
            float c = 0.f;
#pragma unroll
            for (int w = 0; w < 16; w++) c += wsum[w * 32 + lane];
            const int i = lane & 7;
            float d = 0.f;
#pragma unroll
            for (int j = 0; j < 8; j++) {
                float cj = __shfl_sync(0xffffffffu, c, (lane & 24) + j);
                d += Ssh[i * 8 + j] * cj;
            }
            dsh[lane] = d;
        }
        __syncthreads();

        // broadcast-load d (vectorized)
        float dr[4][8];
        {
            const float4* d4 = reinterpret_cast<const float4*>(dsh);
#pragma unroll
            for (int r = 0; r < 4; r++) {
                float4 a = d4[r * 2], b = d4[r * 2 + 1];
                dr[r][0] = a.x; dr[r][1] = a.y; dr[r][2] = a.z; dr[r][3] = a.w;
                dr[r][4] = b.x; dr[r][5] = b.y; dr[r][6] = b.z; dr[r][7] = b.w;
            }
        }

        // rank-8 update: x -= sum_i d_i u_i
#pragma unroll
        for (int i = 0; i < 8; i++) {
            float4 s0 = su4[i * 1024 + tid];
            float4 s1 = su4[i * 1024 + tid + NTHREADS];
#pragma unroll
            for (int r = 0; r < 4; r++) {
                float dd = dr[r][i];
                v[r][0].x -= dd * s0.x; v[r][0].y -= dd * s0.y;
                v[r][0].z -= dd * s0.z; v[r][0].w -= dd * s0.w;
                v[r][1].x -= dd * s1.x; v[r][1].y -= dd * s1.y;
                v[r][1].z -= dd * s1.z; v[r][1].w -= dd * s1.w;
            }
        }

        // streaming store
        {
            float4* y4 = reinterpret_cast<float4*>(Y) + (size_t)q * 4096;
#pragma unroll
            for (int r = 0; r < 4; r++) {
                __stcs(&y4[r * 1024 + tid], v[r][0]);
                __stcs(&y4[r * 1024 + tid + NTHREADS], v[r][1]);
            }
        }

        // rotate double buffer
#pragma unroll
        for (int r = 0; r < 4; r++) {
            v[r][0] = v2[r][0];
            v[r][1] = v2[r][1];
        }
    }
}

extern "C" void kernel_launch(void* const* d_in, const int* in_sizes, int n_in,
                              void* d_out, int out_size) {
    const float* X = (const float*)d_in[0];      // (4, 2048, 4096) fp32
    const float* hra_u = (const float*)d_in[1];  // (4096, 8) fp32
    float* Y = (float*)d_out;

    const int nrows = in_sizes[0] / DDIM;        // 8192
    const int nquads = nrows / 4;                // 2048

    const size_t smem_bytes =
        (8 * DDIM + 16 * 32 + 32 + 64 + 36 + 64 + 8) * sizeof(float);
    cudaFuncSetAttribute(hra_kernel,
                         cudaFuncAttributeMaxDynamicSharedMemorySize,
                         (int)smem_bytes);

    hra_kernel<<<GRID, NTHREADS, smem_bytes>>>(X, hra_u, Y, nquads);
}

// round 7
// speedup vs baseline: 1.6070x; 1.5163x over previous
#include <cuda_runtime.h>

#define DDIM 4096
#define NTHREADS 512
#define GRID 148

// ---------------------------------------------------------------------------
// Single persistent kernel, compact-WY form of 8 sequential Householder
// reflections: x_out = x - U d,  d = S c,  c = U^T x,  S = 2*(I+2L)^{-1}.
//
// Phase 0 (per-CTA, redundant, L2-broadcast): Gram matrix of hra_u, column
//   norms, S via forward substitution; stage transposed normalized u in smem.
// Phase 1: grid-strided quads of 4 rows, cp.async smem-pipelined x, packed
//   f32x2 FMAs for dots + rank-8 update, 31-shfl multi-value butterfly.
// smem: su[8*4096] | xbuf[4*4096] | wsum[16*32] | dsh[32] | Ssh[64]
//       | gsh[36] | Gn[64] | rn[8]   (~193.3 KB)
// ---------------------------------------------------------------------------
extern __shared__ float smem[];

typedef unsigned long long u64;

__device__ __forceinline__ u64 ffma2(u64 a, u64 b, u64 c) {
    u64 d;
    asm("fma.rn.f32x2 %0, %1, %2, %3;" : "=l"(d) : "l"(a), "l"(b), "l"(c));
    return d;
}
__device__ __forceinline__ u64 pack2(float lo, float hi) {
    u64 d;
    asm("mov.b64 %0, {%1, %2};" : "=l"(d) : "f"(lo), "f"(hi));
    return d;
}
__device__ __forceinline__ void unpack2(u64 p, float& lo, float& hi) {
    asm("mov.b64 {%0, %1}, %2;" : "=f"(lo), "=f"(hi) : "l"(p));
}

__device__ __forceinline__ int tri_idx(int a, int b) {
    return a * (17 - a) / 2 + (b - a);  // packed upper-tri [36], a <= b
}

__global__ void __launch_bounds__(NTHREADS, 1)
hra_kernel(const float* __restrict__ X, const float* __restrict__ hra_u,
           float* __restrict__ Y, int nquads) {
    float* su   = smem;                   // 8*4096
    float* xbuf = su + 8 * DDIM;          // 4*4096
    float* wsum = xbuf + 4 * DDIM;        // 16*32
    float* dsh  = wsum + 16 * 32;         // 32
    float* Ssh  = dsh + 32;               // 64
    float* gsh  = Ssh + 64;               // 36
    float* Gn   = gsh + 36;               // 64
    float* rn   = Gn + 64;                // 8

    const int tid  = threadIdx.x;
    const int lane = tid & 31;
    const int warp = tid >> 5;

    // ---------------- Phase 0: Gram + S + stage u ----------------
    if (tid < 36) gsh[tid] = 0.f;
    __syncthreads();
    {
        float acc[36];
#pragma unroll
        for (int t = 0; t < 36; t++) acc[t] = 0.f;
        for (int k = tid; k < DDIM; k += NTHREADS) {
            float4 a = reinterpret_cast<const float4*>(hra_u)[k * 2];
            float4 b = reinterpret_cast<const float4*>(hra_u)[k * 2 + 1];
            float v[8] = {a.x, a.y, a.z, a.w, b.x, b.y, b.z, b.w};
            int t = 0;
#pragma unroll
            for (int i = 0; i < 8; i++)
#pragma unroll
                for (int j = i; j < 8; j++)
                    acc[t++] += v[i] * v[j];
        }
#pragma unroll
        for (int t = 0; t < 36; t++) {
#pragma unroll
            for (int o = 16; o > 0; o >>= 1)
                acc[t] += __shfl_xor_sync(0xffffffffu, acc[t], o);
        }
        if (lane == 0)
            for (int t = 0; t < 36; t++) atomicAdd(&gsh[t], acc[t]);
    }
    __syncthreads();
    if (tid < 8) rn[tid] = rsqrtf(gsh[tri_idx(tid, tid)]);
    __syncthreads();
    if (tid < 64) {
        int i = tid >> 3, j = tid & 7;
        int a = i < j ? i : j, b = i < j ? j : i;
        Gn[tid] = gsh[tri_idx(a, b)] * rn[i] * rn[j];
    }
    __syncthreads();
    if (tid < 8) {
        const int c = tid;  // column c of S: solve (I + 2L) x = 2 e_c
        float x[8];
#pragma unroll
        for (int i = 0; i < 8; i++) {
            float s = (i == c) ? 2.f : 0.f;
            for (int j = 0; j < i; j++) s -= 2.f * Gn[j * 8 + i] * x[j];
            x[i] = s;
            Ssh[i * 8 + c] = x[i];
        }
    }
    for (int k = tid; k < DDIM; k += NTHREADS) {
        float4 a = reinterpret_cast<const float4*>(hra_u)[k * 2];
        float4 b = reinterpret_cast<const float4*>(hra_u)[k * 2 + 1];
        float v[8] = {a.x, a.y, a.z, a.w, b.x, b.y, b.z, b.w};
#pragma unroll
        for (int i = 0; i < 8; i++)
            su[i * DDIM + k] = v[i] * rn[i];
    }
    __syncthreads();

    // ---------------- Phase 1: main loop ----------------
    const float4* su4 = reinterpret_cast<const float4*>(su);
    const float4* xb4 = reinterpret_cast<const float4*>(xbuf);
    const int t_self = (int)(__brev((unsigned)lane) >> 27);  // bitrev5(lane)

    // cp.async target addresses for this thread's 8 private slots
    unsigned xb_s0 = (unsigned)__cvta_generic_to_shared(xbuf) + (unsigned)tid * 16u;

    int q = blockIdx.x;
    if (q >= nquads) return;

    // prologue: prefetch first quad
    {
        const float4* xg = reinterpret_cast<const float4*>(X) + (size_t)q * 4096;
#pragma unroll
        for (int r = 0; r < 4; r++) {
#pragma unroll
            for (int h = 0; h < 2; h++) {
                unsigned s = xb_s0 + (unsigned)(r * 1024 + h * NTHREADS) * 16u
                           - (unsigned)tid * 16u + (unsigned)tid * 16u; // slot (r*1024 + h*512 + tid)
                s = (unsigned)__cvta_generic_to_shared(xbuf)
                  + (unsigned)(r * 1024 + h * NTHREADS + tid) * 16u;
                const float4* g = xg + (r * 1024 + h * NTHREADS + tid);
                asm volatile("cp.async.cg.shared.global [%0], [%1], 16;"
                             :: "r"(s), "l"(g));
            }
        }
        asm volatile("cp.async.commit_group;");
    }

    for (; q < nquads; q += GRID) {
        // wait for this quad's data, pull into registers (packed pairs)
        asm volatile("cp.async.wait_group 0;");

        u64 vp[4][4];
#pragma unroll
        for (int r = 0; r < 4; r++) {
#pragma unroll
            for (int h = 0; h < 2; h++) {
                float4 lv = xb4[r * 1024 + h * NTHREADS + tid];
                vp[r][h * 2 + 0] = pack2(lv.x, lv.y);
                vp[r][h * 2 + 1] = pack2(lv.z, lv.w);
            }
        }

        // immediately start prefetch of next quad into the same (private) slots
        {
            int qn = q + GRID;
            int qc = qn < nquads ? qn : q;
            const float4* xg = reinterpret_cast<const float4*>(X) + (size_t)qc * 4096;
#pragma unroll
            for (int r = 0; r < 4; r++) {
#pragma unroll
                for (int h = 0; h < 2; h++) {
                    unsigned s = (unsigned)__cvta_generic_to_shared(xbuf)
                               + (unsigned)(r * 1024 + h * NTHREADS + tid) * 16u;
                    const float4* g = xg + (r * 1024 + h * NTHREADS + tid);
                    asm volatile("cp.async.cg.shared.global [%0], [%1], 16;"
                                 :: "r"(s), "l"(g));
                }
            }
            asm volatile("cp.async.commit_group;");
        }

        // partial dots with packed FMA: acc[r][i] pair, then fold lo+hi
        float val[32];
#pragma unroll
        for (int i = 0; i < 8; i++) {
            float4 s0 = su4[i * 1024 + tid];
            float4 s1 = su4[i * 1024 + tid + NTHREADS];
            u64 sp0 = pack2(s0.x, s0.y), sp1 = pack2(s0.z, s0.w);
            u64 sp2 = pack2(s1.x, s1.y), sp3 = pack2(s1.z, s1.w);
#pragma unroll
            for (int r = 0; r < 4; r++) {
                u64 a0 = ffma2(vp[r][0], sp0, 0ull);
                a0 = ffma2(vp[r][1], sp1, a0);
                a0 = ffma2(vp[r][2], sp2, a0);
                a0 = ffma2(vp[r][3], sp3, a0);
                float lo, hi;
                unpack2(a0, lo, hi);
                val[r * 8 + i] = lo + hi;
            }
        }

        // multi-value butterfly: 31 shfl; lane ends with sum of val[bitrev5(lane)]
#pragma unroll
        for (int s = 0; s < 5; s++) {
            const int m = 1 << s;
            const int h = 16 >> s;
#pragma unroll
            for (int k = 0; k < h; k++) {
                float send = (lane & m) ? val[k] : val[k + h];
                float rec  = __shfl_xor_sync(0xffffffffu, send, m);
                float keep = (lane & m) ? val[k + h] : val[k];
                val[k] = keep + rec;
            }
        }
        wsum[warp * 32 + t_self] = val[0];
        __syncthreads();

        // warp 0: finish cross-warp reduction (c), apply S -> d, publish
        if (warp == 0) {
            float c = 0.f;
#pragma unroll
            for (int w = 0; w < 16; w++) c += wsum[w * 32 + lane];
            const int i = lane & 7;
            float d = 0.f;
#pragma unroll
            for (int j = 0; j < 8; j++) {
                float cj = __shfl_sync(0xffffffffu, c, (lane & 24) + j);
                d += Ssh[i * 8 + j] * cj;
            }
            dsh[lane] = d;
        }
        __syncthreads();

        // broadcast d, negate, pack
        u64 nd2[4][8];
        {
            const float4* d4 = reinterpret_cast<const float4*>(dsh);
#pragma unroll
            for (int r = 0; r < 4; r++) {
                float4 a = d4[r * 2], b = d4[r * 2 + 1];
                float dd[8] = {a.x, a.y, a.z, a.w, b.x, b.y, b.z, b.w};
#pragma unroll
                for (int i = 0; i < 8; i++)
                    nd2[r][i] = pack2(-dd[i], -dd[i]);
            }
        }

        // rank-8 update with packed FMA: x -= sum_i d_i u_i
#pragma unroll
        for (int i = 0; i < 8; i++) {
            float4 s0 = su4[i * 1024 + tid];
            float4 s1 = su4[i * 1024 + tid + NTHREADS];
            u64 sp0 = pack2(s0.x, s0.y), sp1 = pack2(s0.z, s0.w);
            u64 sp2 = pack2(s1.x, s1.y), sp3 = pack2(s1.z, s1.w);
#pragma unroll
            for (int r = 0; r < 4; r++) {
                vp[r][0] = ffma2(nd2[r][i], sp0, vp[r][0]);
                vp[r][1] = ffma2(nd2[r][i], sp1, vp[r][1]);
                vp[r][2] = ffma2(nd2[r][i], sp2, vp[r][2]);
                vp[r][3] = ffma2(nd2[r][i], sp3, vp[r][3]);
            }
        }

        // streaming store
        {
            float4* y4 = reinterpret_cast<float4*>(Y) + (size_t)q * 4096;
#pragma unroll
            for (int r = 0; r < 4; r++) {
#pragma unroll
                for (int h = 0; h < 2; h++) {
                    float4 o;
                    unpack2(vp[r][h * 2 + 0], o.x, o.y);
                    unpack2(vp[r][h * 2 + 1], o.z, o.w);
                    __stcs(&y4[r * 1024 + h * NTHREADS + tid], o);
                }
            }
        }
    }
}

extern "C" void kernel_launch(void* const* d_in, const int* in_sizes, int n_in,
                              void* d_out, int out_size) {
    const float* X = (const float*)d_in[0];      // (4, 2048, 4096) fp32
    const float* hra_u = (const float*)d_in[1];  // (4096, 8) fp32
    float* Y = (float*)d_out;

    const int nrows = in_sizes[0] / DDIM;        // 8192
    const int nquads = nrows / 4;                // 2048

    const size_t smem_bytes =
        (8 * DDIM + 4 * DDIM + 16 * 32 + 32 + 64 + 36 + 64 + 8) * sizeof(float);
    cudaFuncSetAttribute(hra_kernel,
                         cudaFuncAttributeMaxDynamicSharedMemorySize,
                         (int)smem_bytes);

    hra_kernel<<<GRID, NTHREADS, smem_bytes>>>(X, hra_u, Y, nquads);
}

// round 10
// speedup vs baseline: 1.6648x; 1.0360x over previous
#include <cuda_runtime.h>

#define DDIM 4096
#define NTHREADS 512
#define GRID 148
#define R4 4      // rows per iteration
#define NBUF 3    // cp.async pipeline depth

// ---------------------------------------------------------------------------
// Compact-WY form of 8 sequential Householder reflections:
//   x_out = x - U d,  d = S c,  c = U^T x,  S = 2*(I+2L)^{-1}, U normalized.
//
// Persistent kernel, 1 CTA/SM. Each thread holds its 8 elements (float4
// chunks tid and tid+512) of ALL 8 normalized u vectors in registers
// (64 regs) -> zero u smem traffic. X is streamed through a triple-buffered
// smem ring via cp.async (per-thread private slots, wait_group 2 => ~2
// iterations of latency hiding); x is read from smem in BOTH the dot and
// update phases so it never occupies registers across the reduction.
// smem: xbuf[3][4*4096] | wsum[16*32] | dsh2[64] | Ssh[64] | gsh[36] | rn[8]
// ---------------------------------------------------------------------------
extern __shared__ float smem[];

typedef unsigned long long u64;

__device__ __forceinline__ u64 ffma2(u64 a, u64 b, u64 c) {
    u64 d;
    asm("fma.rn.f32x2 %0, %1, %2, %3;" : "=l"(d) : "l"(a), "l"(b), "l"(c));
    return d;
}
__device__ __forceinline__ u64 pack2(float lo, float hi) {
    u64 d;
    asm("mov.b64 %0, {%1, %2};" : "=l"(d) : "f"(lo), "f"(hi));
    return d;
}
__device__ __forceinline__ void unpack2(u64 p, float& lo, float& hi) {
    asm("mov.b64 {%0, %1}, %2;" : "=f"(lo), "=f"(hi) : "l"(p));
}

__device__ __forceinline__ int tri_idx(int a, int b) {
    return a * (17 - a) / 2 + (b - a);  // packed upper-tri [36], a <= b
}

__global__ void __launch_bounds__(NTHREADS, 1)
hra_kernel(const float* __restrict__ X, const float* __restrict__ hra_u,
           float* __restrict__ Y, int nq) {
    float* xbuf = smem;                         // 3 * 4*4096
    float* wsum = xbuf + NBUF * R4 * DDIM;      // 16*32
    float* dsh2 = wsum + 16 * 32;               // 64 (32 u64), 16B-aligned
    float* Ssh  = dsh2 + 64;                    // 64
    float* gsh  = Ssh + 64;                     // 36
    float* rn   = gsh + 36;                     // 8

    const int tid  = threadIdx.x;
    const int lane = tid & 31;
    const int warp = tid >> 5;

    // ---------------- Phase 0: Gram + S + per-thread u registers ----------
    if (tid < 36) gsh[tid] = 0.f;
    __syncthreads();
    {
        float acc[36];
#pragma unroll
        for (int t = 0; t < 36; t++) acc[t] = 0.f;
        for (int k = tid; k < DDIM; k += NTHREADS) {
            float4 a = reinterpret_cast<const float4*>(hra_u)[k * 2];
            float4 b = reinterpret_cast<const float4*>(hra_u)[k * 2 + 1];
            float v[8] = {a.x, a.y, a.z, a.w, b.x, b.y, b.z, b.w};
            int t = 0;
#pragma unroll
            for (int i = 0; i < 8; i++)
#pragma unroll
                for (int j = i; j < 8; j++)
                    acc[t++] += v[i] * v[j];
        }
#pragma unroll
        for (int t = 0; t < 36; t++) {
#pragma unroll
            for (int o = 16; o > 0; o >>= 1)
                acc[t] += __shfl_xor_sync(0xffffffffu, acc[t], o);
        }
        if (lane == 0)
            for (int t = 0; t < 36; t++) atomicAdd(&gsh[t], acc[t]);
    }
    __syncthreads();
    if (tid < 8) rn[tid] = rsqrtf(gsh[tri_idx(tid, tid)]);
    __syncthreads();
    if (tid < 8) {
        const int c = tid;  // column c of S: solve (I + 2L) x = 2 e_c
        float x[8];
#pragma unroll
        for (int i = 0; i < 8; i++) {
            float s = (i == c) ? 2.f : 0.f;
            for (int j = 0; j < i; j++) {
                float gji = gsh[tri_idx(j, i)] * rn[j] * rn[i];
                s -= 2.f * gji * x[j];
            }
            x[i] = s;
            Ssh[i * 8 + c] = x[i];
        }
    }
    __syncthreads();  // rn, Ssh ready

    // per-thread u registers: elements [4*tid, 4*tid+4) (chunk 0) and
    // [2048+4*tid, 2048+4*tid+4) (chunk 1) of each normalized vector.
    // up[i][c*2+p] packs elements (chunk c, 2p),(chunk c, 2p+1) of vector i.
    u64 up[8][4];
    {
        const float4* hu4 = reinterpret_cast<const float4*>(hra_u);
#pragma unroll
        for (int c = 0; c < 2; c++) {
            float uu[4][8];  // [elem in chunk][vec]
#pragma unroll
            for (int e = 0; e < 4; e++) {
                int k = c * 2048 + 4 * tid + e;   // row of hra_u
                float4 t0 = hu4[k * 2 + 0];
                float4 t1 = hu4[k * 2 + 1];
                uu[e][0] = t0.x; uu[e][1] = t0.y; uu[e][2] = t0.z; uu[e][3] = t0.w;
                uu[e][4] = t1.x; uu[e][5] = t1.y; uu[e][6] = t1.z; uu[e][7] = t1.w;
            }
#pragma unroll
            for (int i = 0; i < 8; i++) {
                float r = rn[i];
                up[i][c * 2 + 0] = pack2(uu[0][i] * r, uu[1][i] * r);
                up[i][c * 2 + 1] = pack2(uu[2][i] * r, uu[3][i] * r);
            }
        }
    }

    // ---------------- Phase 1: main loop (4 rows / iteration) --------------
    const int t_self = (int)(__brev((unsigned)lane) >> 27);  // bitrev5(lane)
    const unsigned xb_base = (unsigned)__cvta_generic_to_shared(xbuf);
    const unsigned BUF_BYTES = R4 * DDIM * 4u;

    int q = blockIdx.x;
    if (q >= nq) return;

    // prologue: prefetch q -> buf0, q+GRID -> buf1
#pragma unroll
    for (int pb = 0; pb < 2; pb++) {
        int qp = q + pb * GRID;
        int qc = qp < nq ? qp : q;
        const float4* xg = reinterpret_cast<const float4*>(X) + (size_t)qc * 4096;
#pragma unroll
        for (int r = 0; r < R4; r++) {
#pragma unroll
            for (int h = 0; h < 2; h++) {
                unsigned s = xb_base + pb * BUF_BYTES
                           + (unsigned)(r * 1024 + h * NTHREADS + tid) * 16u;
                const float4* g = xg + (r * 1024 + h * NTHREADS + tid);
                asm volatile("cp.async.cg.shared.global [%0], [%1], 16;"
                             :: "r"(s), "l"(g));
            }
        }
        asm volatile("cp.async.commit_group;");
    }

    int bcur = 0;
    for (; q < nq; q += GRID) {
        // prefetch q+2*GRID into buffer (bcur+2)%3
        {
            int bpf = bcur + 2; if (bpf >= NBUF) bpf -= NBUF;
            int qp = q + 2 * GRID;
            int qc = qp < nq ? qp : q;
            const float4* xg = reinterpret_cast<const float4*>(X) + (size_t)qc * 4096;
#pragma unroll
            for (int r = 0; r < R4; r++) {
#pragma unroll
                for (int h = 0; h < 2; h++) {
                    unsigned s = xb_base + bpf * BUF_BYTES
                               + (unsigned)(r * 1024 + h * NTHREADS + tid) * 16u;
                    const float4* g = xg + (r * 1024 + h * NTHREADS + tid);
                    asm volatile("cp.async.cg.shared.global [%0], [%1], 16;"
                                 :: "r"(s), "l"(g));
                }
            }
            asm volatile("cp.async.commit_group;");
        }
        // wait until the group for the current buffer has landed
        asm volatile("cp.async.wait_group 2;");

        // row r occupies float4/u64x2 slots [r*1024, (r+1)*1024) of this buffer
        const ulonglong2* xb2 =
            reinterpret_cast<const ulonglong2*>(xbuf + bcur * (R4 * DDIM));

        // dots: val[r*8+i] = <x_r(thread chunks), u_i(thread chunks)>
        float val[32];
#pragma unroll
        for (int r = 0; r < R4; r++) {
            ulonglong2 xa = xb2[r * 1024 + tid];            // chunk 0
            ulonglong2 xc = xb2[r * 1024 + tid + NTHREADS]; // chunk 1
#pragma unroll
            for (int i = 0; i < 8; i++) {
                u64 a0 = ffma2(xa.x, up[i][0], 0ull);
                a0 = ffma2(xa.y, up[i][1], a0);
                a0 = ffma2(xc.x, up[i][2], a0);
                a0 = ffma2(xc.y, up[i][3], a0);
                float lo, hi;
                unpack2(a0, lo, hi);
                val[r * 8 + i] = lo + hi;
            }
        }

        // 31-shfl multi-value butterfly; lane ends with sum of val[bitrev5(lane)]
#pragma unroll
        for (int s = 0; s < 5; s++) {
            const int m = 1 << s;
            const int h = 16 >> s;
#pragma unroll
            for (int k = 0; k < h; k++) {
                float send = (lane & m) ? val[k] : val[k + h];
                float rec  = __shfl_xor_sync(0xffffffffu, send, m);
                float keep = (lane & m) ? val[k + h] : val[k];
                val[k] = keep + rec;
            }
        }
        wsum[warp * 32 + t_self] = val[0];
        __syncthreads();

        // warp 0: finish cross-warp reduction (c), apply S -> d,
        // publish negated duplicated f32x2 pairs
        if (warp == 0) {
            float c = 0.f;
#pragma unroll
            for (int w = 0; w < 16; w++) c += wsum[w * 32 + lane];
            const int i = lane & 7;
            float d = 0.f;
#pragma unroll
            for (int j = 0; j < 8; j++) {
                float cj = __shfl_sync(0xffffffffu, c, (lane & 24) + j);
                d += Ssh[i * 8 + j] * cj;
            }
            reinterpret_cast<u64*>(dsh2)[lane] = pack2(-d, -d);  // [row*8+i]
        }
        __syncthreads();

        // rank-8 update + streaming store (x re-read from smem)
        {
            const ulonglong2* dq = reinterpret_cast<const ulonglong2*>(dsh2);
            float4* y4 = reinterpret_cast<float4*>(Y) + (size_t)q * 4096;
#pragma unroll
            for (int r = 0; r < R4; r++) {
                ulonglong2 p0 = dq[r * 4 + 0];
                ulonglong2 p1 = dq[r * 4 + 1];
                ulonglong2 p2 = dq[r * 4 + 2];
                ulonglong2 p3 = dq[r * 4 + 3];
                u64 nd[8] = {p0.x, p0.y, p1.x, p1.y, p2.x, p2.y, p3.x, p3.y};

                ulonglong2 xa = xb2[r * 1024 + tid];
                ulonglong2 xc = xb2[r * 1024 + tid + NTHREADS];
                u64 w0 = xa.x, w1 = xa.y, w2 = xc.x, w3 = xc.y;
#pragma unroll
                for (int i = 0; i < 8; i++) {
                    w0 = ffma2(nd[i], up[i][0], w0);
                    w1 = ffma2(nd[i], up[i][1], w1);
                    w2 = ffma2(nd[i], up[i][2], w2);
                    w3 = ffma2(nd[i], up[i][3], w3);
                }
                float4 o0, o1;
                unpack2(w0, o0.x, o0.y); unpack2(w1, o0.z, o0.w);
                unpack2(w2, o1.x, o1.y); unpack2(w3, o1.z, o1.w);
                __stcs(&y4[r * 1024 + tid], o0);
                __stcs(&y4[r * 1024 + tid + NTHREADS], o1);
            }
        }

        if (++bcur == NBUF) bcur = 0;
    }
}

extern "C" void kernel_launch(void* const* d_in, const int* in_sizes, int n_in,
                              void* d_out, int out_size) {
    const float* X = (const float*)d_in[0];      // (4, 2048, 4096) fp32
    const float* hra_u = (const float*)d_in[1];  // (4096, 8) fp32
    float* Y = (float*)d_out;

    const int nrows = in_sizes[0] / DDIM;        // 8192
    const int nq = nrows / R4;                   // 2048

    const size_t smem_bytes =
        (NBUF * R4 * DDIM + 16 * 32 + 64 + 64 + 36 + 8) * sizeof(float);
    cudaFuncSetAttribute(hra_kernel,
                         cudaFuncAttributeMaxDynamicSharedMemorySize,
                         (int)smem_bytes);

    hra_kernel<<<GRID, NTHREADS, smem_bytes>>>(X, hra_u, Y, nq);
}